// round 1
// baseline (speedup 1.0000x reference)
#include <cuda_runtime.h>

// Problem constants (match reference_code)
#define NE      262144      // number of edges (E)
#define NMAT    8192        // adjacency matrix side (N)
#define EPSV    1e-8f

#define NBLOCKS 256
#define NTHREADS 256
#define EDGES_PER_BLOCK (NE / NBLOCKS)   // 1024
#define UNROLL (EDGES_PER_BLOCK / NTHREADS) // 4

// Partial sums per block — device globals (no allocation allowed).
__device__ double g_part_pos[NBLOCKS];
__device__ double g_part_neg[NBLOCKS];

__global__ void __launch_bounds__(NTHREADS)
gather_reduce_kernel(const float* __restrict__ adj,
                     const int*   __restrict__ edge_index,  // [2, E]: src row then dst row
                     const int*   __restrict__ neg_edges)   // [E, 2] row-major
{
    const int tid = threadIdx.x;
    const int bid = blockIdx.x;
    const int base = bid * EDGES_PER_BLOCK;

    // Load all indices first, then issue all 8 gathers back-to-back (MLP).
    int s[UNROLL], d[UNROLL];
    int2 nc[UNROLL];
#pragma unroll
    for (int k = 0; k < UNROLL; k++) {
        int i = base + k * NTHREADS + tid;
        s[k]  = __ldg(&edge_index[i]);
        d[k]  = __ldg(&edge_index[NE + i]);
        nc[k] = __ldg(&((const int2*)neg_edges)[i]);
    }

    float p[UNROLL], q[UNROLL];
#pragma unroll
    for (int k = 0; k < UNROLL; k++) {
        p[k] = __ldg(&adj[(long long)s[k] * NMAT + d[k]]);
        q[k] = __ldg(&adj[(long long)nc[k].x * NMAT + nc[k].y]);
    }

    float pos = 0.f, neg = 0.f;
#pragma unroll
    for (int k = 0; k < UNROLL; k++) {
        pos += logf(p[k] + EPSV);
        neg += logf(1.0f - q[k] + EPSV);
    }

    // Warp reduction (float is plenty for 32 values of O(1) magnitude)
#pragma unroll
    for (int off = 16; off > 0; off >>= 1) {
        pos += __shfl_down_sync(0xFFFFFFFFu, pos, off);
        neg += __shfl_down_sync(0xFFFFFFFFu, neg, off);
    }

    __shared__ float s_pos[NTHREADS / 32];
    __shared__ float s_neg[NTHREADS / 32];
    const int lane = tid & 31;
    const int wid  = tid >> 5;
    if (lane == 0) { s_pos[wid] = pos; s_neg[wid] = neg; }
    __syncthreads();

    if (tid == 0) {
        double dp = 0.0, dn = 0.0;
#pragma unroll
        for (int w = 0; w < NTHREADS / 32; w++) {
            dp += (double)s_pos[w];
            dn += (double)s_neg[w];
        }
        g_part_pos[bid] = dp;
        g_part_neg[bid] = dn;
    }
}

__global__ void __launch_bounds__(NBLOCKS)
finalize_kernel(const float* __restrict__ codebook_loss, float* __restrict__ out)
{
    __shared__ double sp[NBLOCKS];
    __shared__ double sn[NBLOCKS];
    const int t = threadIdx.x;
    sp[t] = g_part_pos[t];
    sn[t] = g_part_neg[t];
    __syncthreads();
#pragma unroll
    for (int s = NBLOCKS / 2; s > 0; s >>= 1) {
        if (t < s) { sp[t] += sp[t + s]; sn[t] += sn[t + s]; }
        __syncthreads();
    }
    if (t == 0) {
        double pos_loss = -sp[0] / (double)NE;
        double neg_loss = -sn[0] / (double)NE;
        double loss = pos_loss + neg_loss
                    + (double)codebook_loss[0] + (double)codebook_loss[1]
                    + (double)codebook_loss[2] + (double)codebook_loss[3];
        out[0] = (float)loss;
    }
}

extern "C" void kernel_launch(void* const* d_in, const int* in_sizes, int n_in,
                              void* d_out, int out_size)
{
    const float* adj        = (const float*)d_in[0];   // [N*N] fp32
    const float* codebook   = (const float*)d_in[1];   // [6] fp32
    const int*   edge_index = (const int*)d_in[2];     // [2*E] int32
    const int*   neg_edges  = (const int*)d_in[3];     // [E*2] int32
    float* out = (float*)d_out;

    gather_reduce_kernel<<<NBLOCKS, NTHREADS>>>(adj, edge_index, neg_edges);
    finalize_kernel<<<1, NBLOCKS>>>(codebook, out);
}

// round 2
// speedup vs baseline: 1.0194x; 1.0194x over previous
#include <cuda_runtime.h>

// Problem constants (match reference_code)
#define NE      262144      // number of edges (E)
#define NMAT    8192        // adjacency matrix side (N)
#define EPSV    1e-8f

#define NBLOCKS 256
#define NTHREADS 256
#define EPB     (NE / NBLOCKS)        // 1024 edges per block
#define UNROLL  (EPB / NTHREADS)      // 4

// Scratch: per-block partials + completion ticket (device globals: no allocation).
__device__ double       g_part_pos[NBLOCKS];
__device__ double       g_part_neg[NBLOCKS];
__device__ unsigned int g_count;      // zero-initialized; reset by last block each run

__global__ void __launch_bounds__(NTHREADS)
fused_loss_kernel(const float* __restrict__ adj,
                  const int*   __restrict__ edge_index,   // [2, E]
                  const int*   __restrict__ neg_edges,    // [E, 2]
                  const float* __restrict__ codebook,
                  float*       __restrict__ out)
{
    const int tid  = threadIdx.x;
    const int bid  = blockIdx.x;
    const int base = bid * EPB;

    // ---- Phase 1: indices first, then all 8 gathers back-to-back (max MLP) ----
    int s[UNROLL], d[UNROLL];
    int2 nc[UNROLL];
#pragma unroll
    for (int k = 0; k < UNROLL; k++) {
        int i = base + k * NTHREADS + tid;
        s[k]  = __ldg(&edge_index[i]);
        d[k]  = __ldg(&edge_index[NE + i]);
        nc[k] = __ldg(&((const int2*)neg_edges)[i]);
    }

    float p[UNROLL], q[UNROLL];
#pragma unroll
    for (int k = 0; k < UNROLL; k++) {
        p[k] = __ldg(&adj[(long long)s[k]    * NMAT + d[k]]);
        q[k] = __ldg(&adj[(long long)nc[k].x * NMAT + nc[k].y]);
    }

    // ---- Phase 2: fold 4 logs into 1 via product (range [1e-32, ~1] -> safe) ----
    float pprod = (p[0] + EPSV) * (p[1] + EPSV) * (p[2] + EPSV) * (p[3] + EPSV);
    float qprod = (1.0f - q[0] + EPSV) * (1.0f - q[1] + EPSV)
                * (1.0f - q[2] + EPSV) * (1.0f - q[3] + EPSV);
    float pos = __logf(pprod);
    float neg = __logf(qprod);

    // ---- Phase 3: block reduction ----
#pragma unroll
    for (int off = 16; off > 0; off >>= 1) {
        pos += __shfl_down_sync(0xFFFFFFFFu, pos, off);
        neg += __shfl_down_sync(0xFFFFFFFFu, neg, off);
    }
    __shared__ float s_pos[NTHREADS / 32];
    __shared__ float s_neg[NTHREADS / 32];
    const int lane = tid & 31;
    const int wid  = tid >> 5;
    if (lane == 0) { s_pos[wid] = pos; s_neg[wid] = neg; }
    __syncthreads();

    if (tid == 0) {
        double dp = 0.0, dn = 0.0;
#pragma unroll
        for (int w = 0; w < NTHREADS / 32; w++) {
            dp += (double)s_pos[w];
            dn += (double)s_neg[w];
        }
        g_part_pos[bid] = dp;
        g_part_neg[bid] = dn;
    }

    // ---- Phase 4: last-block-done final reduction (deterministic) ----
    __shared__ unsigned int s_ticket;
    __threadfence();   // tid0: partial store is visible device-wide before ticket
    if (tid == 0) s_ticket = atomicAdd(&g_count, 1u);
    __syncthreads();

    if (s_ticket == NBLOCKS - 1) {
        // volatile loads -> strong, bypass L1 (partials written by other SMs)
        double dp = ((volatile double*)g_part_pos)[tid];
        double dn = ((volatile double*)g_part_neg)[tid];
#pragma unroll
        for (int off = 16; off > 0; off >>= 1) {
            dp += __shfl_down_sync(0xFFFFFFFFu, dp, off);
            dn += __shfl_down_sync(0xFFFFFFFFu, dn, off);
        }
        __shared__ double f_pos[NTHREADS / 32];
        __shared__ double f_neg[NTHREADS / 32];
        if (lane == 0) { f_pos[wid] = dp; f_neg[wid] = dn; }
        __syncthreads();

        if (tid == 0) {
            double tp = 0.0, tn = 0.0;
#pragma unroll
            for (int w = 0; w < NTHREADS / 32; w++) { tp += f_pos[w]; tn += f_neg[w]; }
            double pos_loss = -tp / (double)NE;
            double neg_loss = -tn / (double)NE;
            double loss = pos_loss + neg_loss
                        + (double)codebook[0] + (double)codebook[1]
                        + (double)codebook[2] + (double)codebook[3];
            out[0]  = (float)loss;
            g_count = 0;   // reset ticket for the next graph replay
        }
    }
}

extern "C" void kernel_launch(void* const* d_in, const int* in_sizes, int n_in,
                              void* d_out, int out_size)
{
    const float* adj        = (const float*)d_in[0];   // [N*N] fp32
    const float* codebook   = (const float*)d_in[1];   // [6] fp32
    const int*   edge_index = (const int*)d_in[2];     // [2*E] int32
    const int*   neg_edges  = (const int*)d_in[3];     // [E*2] int32
    float* out = (float*)d_out;

    fused_loss_kernel<<<NBLOCKS, NTHREADS>>>(adj, edge_index, neg_edges, codebook, out);
}

// round 3
// speedup vs baseline: 1.0419x; 1.0221x over previous
#include <cuda_runtime.h>

#define NE      262144      // edges
#define NMAT    8192        // adjacency side
#define EPSV    1e-8f

#define NBLOCKS  512
#define NTHREADS 256
#define EPB      (NE / NBLOCKS)          // 512 edges per block
#define EPT      2                        // edges per thread (2 pos + 2 neg gathers)

#define FXSCALE 16777216.0               // 2^24 fixed-point scale

// Deterministic integer accumulators + completion ticket (device globals).
__device__ unsigned long long g_acc_pos;   // zero-init; reset by last block
__device__ unsigned long long g_acc_neg;
__device__ unsigned int       g_count;

__global__ void __launch_bounds__(NTHREADS)
fused_loss_kernel(const float* __restrict__ adj,
                  const int*   __restrict__ edge_index,   // [2, E]
                  const int*   __restrict__ neg_edges,    // [E, 2]
                  const float* __restrict__ codebook,
                  float*       __restrict__ out)
{
    const int tid  = threadIdx.x;
    const int bid  = blockIdx.x;
    // This thread owns edges e0 = base + 2*tid, e0+1  (contiguous pair -> vector index loads)
    const int e0   = bid * EPB + 2 * tid;

    // ---- Phase 1: vectorized index loads (3 instructions), then 4 gathers back-to-back ----
    const int2 src = __ldg((const int2*)&edge_index[e0]);        // src[e0], src[e0+1]
    const int2 dst = __ldg((const int2*)&edge_index[NE + e0]);   // dst[e0], dst[e0+1]
    const int4 ng  = __ldg((const int4*)&neg_edges[2 * e0]);     // (r0,c0,r1,c1)

    const float p0 = __ldcg(&adj[(long long)src.x * NMAT + dst.x]);
    const float p1 = __ldcg(&adj[(long long)src.y * NMAT + dst.y]);
    const float q0 = __ldcg(&adj[(long long)ng.x  * NMAT + ng.y]);
    const float q1 = __ldcg(&adj[(long long)ng.z  * NMAT + ng.w]);

    // ---- Phase 2: fold 2 logs into 1 via product (range [1e-16, ~1] -> safe in fp32) ----
    float pos = __logf((p0 + EPSV) * (p1 + EPSV));
    float neg = __logf((1.0f - q0 + EPSV) * (1.0f - q1 + EPSV));

    // ---- Phase 3: warp + block reduction (float), quantize once per block ----
#pragma unroll
    for (int off = 16; off > 0; off >>= 1) {
        pos += __shfl_down_sync(0xFFFFFFFFu, pos, off);
        neg += __shfl_down_sync(0xFFFFFFFFu, neg, off);
    }
    __shared__ float s_pos[NTHREADS / 32];
    __shared__ float s_neg[NTHREADS / 32];
    const int lane = tid & 31;
    const int wid  = tid >> 5;
    if (lane == 0) { s_pos[wid] = pos; s_neg[wid] = neg; }
    __syncthreads();

    if (tid == 0) {
        double dp = 0.0, dn = 0.0;
#pragma unroll
        for (int w = 0; w < NTHREADS / 32; w++) {
            dp += (double)s_pos[w];
            dn += (double)s_neg[w];
        }
        // Exact, order-independent integer accumulation (deterministic).
        long long ip = llrint(dp * FXSCALE);
        long long in = llrint(dn * FXSCALE);
        atomicAdd(&g_acc_pos, (unsigned long long)ip);
        atomicAdd(&g_acc_neg, (unsigned long long)in);
        __threadfence();
        unsigned int ticket = atomicAdd(&g_count, 1u);

        // ---- Phase 4: last block finalizes (tiny tail: two u64 reads) ----
        if (ticket == NBLOCKS - 1) {
            unsigned long long up = atomicAdd(&g_acc_pos, 0ULL);  // strong read
            unsigned long long un = atomicAdd(&g_acc_neg, 0ULL);
            double tp = (double)(long long)up / FXSCALE;
            double tn = (double)(long long)un / FXSCALE;
            double loss = (-tp - tn) / (double)NE
                        + (double)codebook[0] + (double)codebook[1]
                        + (double)codebook[2] + (double)codebook[3];
            out[0] = (float)loss;
            // Reset scratch for the next graph replay (same stream -> ordered).
            g_acc_pos = 0ULL;
            g_acc_neg = 0ULL;
            __threadfence();
            g_count = 0;
        }
    }
}

extern "C" void kernel_launch(void* const* d_in, const int* in_sizes, int n_in,
                              void* d_out, int out_size)
{
    const float* adj        = (const float*)d_in[0];   // [N*N] fp32
    const float* codebook   = (const float*)d_in[1];   // [6] fp32
    const int*   edge_index = (const int*)d_in[2];     // [2*E] int32
    const int*   neg_edges  = (const int*)d_in[3];     // [E*2] int32
    float* out = (float*)d_out;

    fused_loss_kernel<<<NBLOCKS, NTHREADS>>>(adj, edge_index, neg_edges, codebook, out);
}